// round 13
// baseline (speedup 1.0000x reference)
#include <cuda_runtime.h>
#include <cuda_bf16.h>
#include <cstdint>

#define NROWS 200000
#define NTILES 3125          // 200000 / 64
#define BM 64
#define LDIM 480

// ============================ HMMA helpers ============================
__device__ __forceinline__ void mma_bf16(float& c0, float& c1, float& c2, float& c3,
                                         uint32_t a0, uint32_t a1, uint32_t a2, uint32_t a3,
                                         uint32_t b0, uint32_t b1)
{
    asm volatile("mma.sync.aligned.m16n8k16.row.col.f32.bf16.bf16.f32 "
                 "{%0,%1,%2,%3}, {%4,%5,%6,%7}, {%8,%9}, {%0,%1,%2,%3};"
                 : "+f"(c0), "+f"(c1), "+f"(c2), "+f"(c3)
                 : "r"(a0), "r"(a1), "r"(a2), "r"(a3), "r"(b0), "r"(b1));
}

__device__ __forceinline__ uint32_t pack_hi(float x, float y, float& rx, float& ry) {
    __nv_bfloat162 h = __float22bfloat162_rn(make_float2(x, y));
    float2 hf = __bfloat1622float2(h);
    rx = x - hf.x; ry = y - hf.y;
    return *(uint32_t*)&h;
}
__device__ __forceinline__ uint32_t pack_lo(float rx, float ry) {
    __nv_bfloat162 l = __float22bfloat162_rn(make_float2(rx, ry));
    return *(uint32_t*)&l;
}

__device__ __forceinline__ void cp_async16(uint32_t dst, const void* src, bool pred) {
    int sz = pred ? 16 : 0;
    asm volatile("cp.async.cg.shared.global [%0], [%1], 16, %2;"
                 :: "r"(dst), "l"(src), "r"(sz) : "memory");
}
#define CP_COMMIT()  asm volatile("cp.async.commit_group;" ::: "memory")
#define CP_WAIT(n)   asm volatile("cp.async.wait_group %0;" :: "n"(n) : "memory")

// ============================================================================
// Kernel 0 (R10 passing version, unchanged): out[:, 0:128]
// ============================================================================
#define T0_TILES 1563
#define BM0 128
#define K0_AST 136
#define K0_B0   0
#define K0_BIL  512
#define K0_BROW 68
#define K0_A0   70144
#define K0_A1   139776
#define K0_SMEM 209408

__global__ void __launch_bounds__(512, 1)
k0_mma(const float* __restrict__ x, const float* __restrict__ w0,
       const float* __restrict__ b0, float* __restrict__ out)
{
    extern __shared__ char smem[];
    float* b0s = (float*)(smem + K0_B0);
    uint2* bil = (uint2*)(smem + K0_BIL);

    const int tid  = threadIdx.x;
    const int wid  = tid >> 5;
    const int lane = tid & 31;
    const float a0 = 0.08838834764831845f;

    for (int idx = tid; idx < 128 * 64; idx += 512) {
        int n = idx & 127, kp = idx >> 7;
        float v0 = a0 * w0[(2 * kp) * 128 + n];
        float v1 = a0 * w0[(2 * kp + 1) * 128 + n];
        float r0, r1;
        uint32_t hi = pack_hi(v0, v1, r0, r1);
        uint32_t lo = pack_lo(r0, r1);
        bil[n * K0_BROW + kp] = make_uint2(hi, lo);
    }
    if (tid < 128) b0s[tid] = b0[tid];
    __syncthreads();

    const int mh = wid >> 2;
    const int ns = wid & 3;
    const int lq = lane >> 2;
    const int kq = lane & 3;
    const int ak = kq * 2;

    const uint32_t abase0 = (uint32_t)__cvta_generic_to_shared(smem + K0_A0);
    const uint32_t abase1 = (uint32_t)__cvta_generic_to_shared(smem + K0_A1);

    int t = blockIdx.x;
    if (t < T0_TILES) {
        const int row0 = t * BM0;
        #pragma unroll
        for (int it = 0; it < 8; it++) {
            int i = tid + it * 512;
            int r = i >> 5, c4 = (i & 31) << 2;
            int grow = row0 + r;
            bool p = grow < NROWS;
            const float* src = x + (size_t)(p ? grow : 0) * LDIM + c4;
            cp_async16(abase0 + (uint32_t)(r * K0_AST + c4) * 4u, src, p);
        }
        CP_COMMIT();
    }

    int cur = 0;
    for (; t < T0_TILES; t += gridDim.x) {
        const int row0 = t * BM0;
        const int tn = t + gridDim.x;

        if (tn < T0_TILES) {
            const int nrow0 = tn * BM0;
            const uint32_t nb = cur ? abase0 : abase1;
            #pragma unroll
            for (int it = 0; it < 8; it++) {
                int i = tid + it * 512;
                int r = i >> 5, c4 = (i & 31) << 2;
                int grow = nrow0 + r;
                bool p = grow < NROWS;
                const float* src = x + (size_t)(p ? grow : 0) * LDIM + c4;
                cp_async16(nb + (uint32_t)(r * K0_AST + c4) * 4u, src, p);
            }
            CP_COMMIT();
            CP_WAIT(1);
        } else {
            CP_WAIT(0);
        }
        __syncthreads();

        const float* A = (const float*)(smem + (cur ? K0_A1 : K0_A0));

        float C[2][4][4];
        #pragma unroll
        for (int nt = 0; nt < 4; nt++) {
            float bias0 = b0s[ns * 32 + nt * 8 + ak];
            float bias1 = b0s[ns * 32 + nt * 8 + ak + 1];
            #pragma unroll
            for (int mt = 0; mt < 2; mt++) {
                C[mt][nt][0] = bias0; C[mt][nt][1] = bias1;
                C[mt][nt][2] = bias0; C[mt][nt][3] = bias1;
            }
        }

        #pragma unroll
        for (int ks = 0; ks < 8; ks++) {
            uint32_t ah[2][4], al[2][4];
            #pragma unroll
            for (int mt = 0; mt < 2; mt++) {
                const int ar = mh * 32 + mt * 16 + lq;
                const float* ap = A + ar * K0_AST + ak + ks * 16;
                float2 f0 = *(const float2*)(ap);
                float2 f1 = *(const float2*)(ap + 8 * K0_AST);
                float2 f2 = *(const float2*)(ap + 8);
                float2 f3 = *(const float2*)(ap + 8 * K0_AST + 8);
                float rx, ry;
                ah[mt][0] = pack_hi(f0.x, f0.y, rx, ry); al[mt][0] = pack_lo(rx, ry);
                ah[mt][1] = pack_hi(f1.x, f1.y, rx, ry); al[mt][1] = pack_lo(rx, ry);
                ah[mt][2] = pack_hi(f2.x, f2.y, rx, ry); al[mt][2] = pack_lo(rx, ry);
                ah[mt][3] = pack_hi(f3.x, f3.y, rx, ry); al[mt][3] = pack_lo(rx, ry);
            }

            const int kpb = ks * 8 + kq;
            #pragma unroll
            for (int nt = 0; nt < 4; nt++) {
                const uint2* brow = bil + (ns * 32 + nt * 8 + lq) * K0_BROW;
                uint2 bv0 = brow[kpb];
                uint2 bv1 = brow[kpb + 4];
                #pragma unroll
                for (int mt = 0; mt < 2; mt++) {
                    mma_bf16(C[mt][nt][0], C[mt][nt][1], C[mt][nt][2], C[mt][nt][3],
                             ah[mt][0], ah[mt][1], ah[mt][2], ah[mt][3], bv0.x, bv1.x);
                    mma_bf16(C[mt][nt][0], C[mt][nt][1], C[mt][nt][2], C[mt][nt][3],
                             al[mt][0], al[mt][1], al[mt][2], al[mt][3], bv0.x, bv1.x);
                    mma_bf16(C[mt][nt][0], C[mt][nt][1], C[mt][nt][2], C[mt][nt][3],
                             ah[mt][0], ah[mt][1], ah[mt][2], ah[mt][3], bv0.y, bv1.y);
                }
            }
        }

        #pragma unroll
        for (int mt = 0; mt < 2; mt++) {
            const int grow = row0 + mh * 32 + mt * 16 + lq;
            #pragma unroll
            for (int nt = 0; nt < 4; nt++) {
                float* o0 = out + (size_t)grow * LDIM + ns * 32 + nt * 8 + ak;
                if (grow < NROWS)
                    *(float2*)o0 = make_float2(C[mt][nt][0], C[mt][nt][1]);
                if (grow + 8 < NROWS)
                    *(float2*)(o0 + 8 * LDIM) = make_float2(C[mt][nt][2], C[mt][nt][3]);
            }
        }
        __syncthreads();
        cur ^= 1;
    }
}

// ============================================================================
// Kernel 1 (cp.async pipeline): out[:, 128+3w+i], i=0..2
// 512 threads, 1 CTA/SM, BM=64. 16 warps = 4 m-tiles x 4 n-quads.
// fp32 x slice double-buffered via cp.async; bf16 hi/lo at fragment load.
// C scattered into the consumed buffer (overlay), then coalesced store.
// smem: B_il[0,18432) A0[18432,68608) A1[68608,118784), stride 196 floats
// ============================================================================
#define K1_BROW 36            // uint2 per B row (32 kp + pad)
#define K1_A0   18432
#define K1_A1   68608
#define K1_AST  196
#define K1_SMEM 118784

__global__ void __launch_bounds__(512, 1)
k1_mma(const float* __restrict__ x, const float* __restrict__ w1,
       float* __restrict__ out)
{
    extern __shared__ char smem[];
    uint2* bil = (uint2*)smem;

    const int tid  = threadIdx.x;
    const int wid  = tid >> 5;
    const int lane = tid & 31;
    const float a1 = 0.125f;   // 1/sqrt(64)

    // B[n=w][kp=u-pair] interleaved {hi, lo}
    for (int idx = tid; idx < 64 * 32; idx += 512) {
        int n = idx & 63, kp = idx >> 6;
        float v0 = a1 * w1[(2 * kp) * 64 + n];
        float v1 = a1 * w1[(2 * kp + 1) * 64 + n];
        float r0, r1;
        uint32_t hi = pack_hi(v0, v1, r0, r1);
        uint32_t lo = pack_lo(r0, r1);
        bil[n * K1_BROW + kp] = make_uint2(hi, lo);
    }

    const int mt = wid >> 2;       // m-tile 0..3 (16 rows)
    const int nq = wid & 3;        // n-quad 0..3 (2 n-tiles each)
    const int lq = lane >> 2;
    const int kq = lane & 3;
    const int np = (lane & 3) * 2;

    const uint32_t ab0 = (uint32_t)__cvta_generic_to_shared(smem + K1_A0);
    const uint32_t ab1 = (uint32_t)__cvta_generic_to_shared(smem + K1_A1);

    int t = blockIdx.x;
    if (t < NTILES) {
        const int row0 = t * BM;
        #pragma unroll
        for (int it = 0; it < 6; it++) {
            int i = tid + it * 512;
            int r = i / 48, c4 = (i - r * 48) * 4;
            cp_async16(ab0 + (uint32_t)(r * K1_AST + c4) * 4u,
                       x + (size_t)(row0 + r) * LDIM + 128 + c4, true);
        }
        CP_COMMIT();
    }
    __syncthreads();   // bil visible to all

    int cur = 0;
    for (; t < NTILES; t += gridDim.x) {
        const int row0 = t * BM;
        const int tn = t + gridDim.x;

        if (tn < NTILES) {
            const int nrow0 = tn * BM;
            const uint32_t nb = cur ? ab0 : ab1;
            #pragma unroll
            for (int it = 0; it < 6; it++) {
                int i = tid + it * 512;
                int r = i / 48, c4 = (i - r * 48) * 4;
                cp_async16(nb + (uint32_t)(r * K1_AST + c4) * 4u,
                           x + (size_t)(nrow0 + r) * LDIM + 128 + c4, true);
            }
            CP_COMMIT();
            CP_WAIT(1);
        } else {
            CP_WAIT(0);
        }
        __syncthreads();

        const float* xs = (const float*)(smem + (cur ? K1_A1 : K1_A0));

        float C[3][2][4];
        #pragma unroll
        for (int ch = 0; ch < 3; ch++)
            #pragma unroll
            for (int q = 0; q < 2; q++)
                #pragma unroll
                for (int j = 0; j < 4; j++) C[ch][q][j] = 0.f;

        #pragma unroll
        for (int ch = 0; ch < 3; ch++) {
            uint32_t ah[4][4], al[4][4];
            #pragma unroll
            for (int ks = 0; ks < 4; ks++) {
                // A[r][u] = xs[r][3u+ch]; k = 16ks + 2kq -> col 48ks + 6kq + ch
                const float* p0 = xs + (mt * 16 + lq) * K1_AST + 48 * ks + 6 * kq + ch;
                const float* p1 = p0 + 8 * K1_AST;
                float rx, ry;
                ah[ks][0] = pack_hi(p0[0],  p0[3],  rx, ry); al[ks][0] = pack_lo(rx, ry);
                ah[ks][1] = pack_hi(p1[0],  p1[3],  rx, ry); al[ks][1] = pack_lo(rx, ry);
                ah[ks][2] = pack_hi(p0[24], p0[27], rx, ry); al[ks][2] = pack_lo(rx, ry);
                ah[ks][3] = pack_hi(p1[24], p1[27], rx, ry); al[ks][3] = pack_lo(rx, ry);
            }
            #pragma unroll
            for (int q = 0; q < 2; q++) {
                const int nt = nq * 2 + q;
                const uint2* brow = bil + (nt * 8 + lq) * K1_BROW;
                #pragma unroll
                for (int ks = 0; ks < 4; ks++) {
                    const int kpb = ks * 8 + kq;
                    uint2 bv0 = brow[kpb];
                    uint2 bv1 = brow[kpb + 4];
                    mma_bf16(C[ch][q][0], C[ch][q][1], C[ch][q][2], C[ch][q][3],
                             ah[ks][0], ah[ks][1], ah[ks][2], ah[ks][3], bv0.x, bv1.x);
                    mma_bf16(C[ch][q][0], C[ch][q][1], C[ch][q][2], C[ch][q][3],
                             al[ks][0], al[ks][1], al[ks][2], al[ks][3], bv0.x, bv1.x);
                    mma_bf16(C[ch][q][0], C[ch][q][1], C[ch][q][2], C[ch][q][3],
                             ah[ks][0], ah[ks][1], ah[ks][2], ah[ks][3], bv0.y, bv1.y);
                }
            }
        }
        __syncthreads();   // all frag reads of buf[cur] done

        // scatter C into buf[cur] (overlay), then coalesced store
        float* st = (float*)(smem + (cur ? K1_A1 : K1_A0));
        {
            const int rA = mt * 16 + lq;
            #pragma unroll
            for (int ch = 0; ch < 3; ch++) {
                #pragma unroll
                for (int q = 0; q < 2; q++) {
                    const int n0 = (nq * 2 + q) * 8 + np;
                    const int col = 3 * n0 + ch;
                    st[rA * K1_AST + col]           = C[ch][q][0];
                    st[rA * K1_AST + col + 3]       = C[ch][q][1];
                    st[(rA + 8) * K1_AST + col]     = C[ch][q][2];
                    st[(rA + 8) * K1_AST + col + 3] = C[ch][q][3];
                }
            }
        }
        __syncthreads();

        #pragma unroll
        for (int it = 0; it < 6; it++) {
            int i = tid + it * 512;
            int r = i / 48, c4 = (i - r * 48) * 4;
            float4 v = *(const float4*)(st + r * K1_AST + c4);
            *(float4*)(out + (size_t)(row0 + r) * LDIM + 128 + c4) = v;
        }
        __syncthreads();   // store done before next issue overwrites buf[cur]
        cur ^= 1;
    }
}

// ============================================================================
// Kernel 2 (cp.async pipeline): out[:, 320+5w+i], i=0..4
// 256 threads, 2 CTAs/SM, BM=64. 8 warps = 4 m-tiles x 2 n-halves.
// smem: B_il[0,5120) A0[5120,47104) A1[47104,89088), stride 164 floats
// ============================================================================
#define K2_BROW 20            // uint2 per B row (16 kp + pad)
#define K2_A0   5120
#define K2_A1   47104
#define K2_AST  164
#define K2_SMEM 89088

__global__ void __launch_bounds__(256, 2)
k2_mma(const float* __restrict__ x, const float* __restrict__ w2,
       float* __restrict__ out)
{
    extern __shared__ char smem[];
    uint2* bil = (uint2*)smem;

    const int tid  = threadIdx.x;
    const int wid  = tid >> 5;
    const int lane = tid & 31;
    const float a2 = 0.17677669529663687f;  // 1/sqrt(32)

    for (int idx = tid; idx < 32 * 16; idx += 256) {
        int n = idx & 31, kp = idx >> 5;
        float v0 = a2 * w2[(2 * kp) * 32 + n];
        float v1 = a2 * w2[(2 * kp + 1) * 32 + n];
        float r0, r1;
        uint32_t hi = pack_hi(v0, v1, r0, r1);
        uint32_t lo = pack_lo(r0, r1);
        bil[n * K2_BROW + kp] = make_uint2(hi, lo);
    }

    const int mt = wid >> 1;       // m-tile 0..3
    const int nh = wid & 1;        // n-half 0..1 (2 n-tiles each)
    const int lq = lane >> 2;
    const int kq = lane & 3;
    const int np = (lane & 3) * 2;

    const uint32_t ab0 = (uint32_t)__cvta_generic_to_shared(smem + K2_A0);
    const uint32_t ab1 = (uint32_t)__cvta_generic_to_shared(smem + K2_A1);

    int t = blockIdx.x;
    if (t < NTILES) {
        const int row0 = t * BM;
        #pragma unroll
        for (int it = 0; it < 10; it++) {
            int i = tid + it * 256;
            int r = i / 40, c4 = (i - r * 40) * 4;
            cp_async16(ab0 + (uint32_t)(r * K2_AST + c4) * 4u,
                       x + (size_t)(row0 + r) * LDIM + 320 + c4, true);
        }
        CP_COMMIT();
    }
    __syncthreads();

    int cur = 0;
    for (; t < NTILES; t += gridDim.x) {
        const int row0 = t * BM;
        const int tn = t + gridDim.x;

        if (tn < NTILES) {
            const int nrow0 = tn * BM;
            const uint32_t nb = cur ? ab0 : ab1;
            #pragma unroll
            for (int it = 0; it < 10; it++) {
                int i = tid + it * 256;
                int r = i / 40, c4 = (i - r * 40) * 4;
                cp_async16(nb + (uint32_t)(r * K2_AST + c4) * 4u,
                           x + (size_t)(nrow0 + r) * LDIM + 320 + c4, true);
            }
            CP_COMMIT();
            CP_WAIT(1);
        } else {
            CP_WAIT(0);
        }
        __syncthreads();

        const float* xs = (const float*)(smem + (cur ? K2_A1 : K2_A0));

        float C[5][2][4];
        #pragma unroll
        for (int ch = 0; ch < 5; ch++)
            #pragma unroll
            for (int q = 0; q < 2; q++)
                #pragma unroll
                for (int j = 0; j < 4; j++) C[ch][q][j] = 0.f;

        #pragma unroll
        for (int ch = 0; ch < 5; ch++) {
            uint32_t ah[2][4], al[2][4];
            #pragma unroll
            for (int ks = 0; ks < 2; ks++) {
                // A[r][u] = xs[r][5u+ch]; k = 16ks + 2kq -> col 80ks + 10kq + ch
                const float* p0 = xs + (mt * 16 + lq) * K2_AST + 80 * ks + 10 * kq + ch;
                const float* p1 = p0 + 8 * K2_AST;
                float rx, ry;
                ah[ks][0] = pack_hi(p0[0],  p0[5],  rx, ry); al[ks][0] = pack_lo(rx, ry);
                ah[ks][1] = pack_hi(p1[0],  p1[5],  rx, ry); al[ks][1] = pack_lo(rx, ry);
                ah[ks][2] = pack_hi(p0[40], p0[45], rx, ry); al[ks][2] = pack_lo(rx, ry);
                ah[ks][3] = pack_hi(p1[40], p1[45], rx, ry); al[ks][3] = pack_lo(rx, ry);
            }
            #pragma unroll
            for (int q = 0; q < 2; q++) {
                const int nt = nh * 2 + q;
                const uint2* brow = bil + (nt * 8 + lq) * K2_BROW;
                #pragma unroll
                for (int ks = 0; ks < 2; ks++) {
                    const int kpb = ks * 8 + kq;
                    uint2 bv0 = brow[kpb];
                    uint2 bv1 = brow[kpb + 4];
                    mma_bf16(C[ch][q][0], C[ch][q][1], C[ch][q][2], C[ch][q][3],
                             ah[ks][0], ah[ks][1], ah[ks][2], ah[ks][3], bv0.x, bv1.x);
                    mma_bf16(C[ch][q][0], C[ch][q][1], C[ch][q][2], C[ch][q][3],
                             al[ks][0], al[ks][1], al[ks][2], al[ks][3], bv0.x, bv1.x);
                    mma_bf16(C[ch][q][0], C[ch][q][1], C[ch][q][2], C[ch][q][3],
                             ah[ks][0], ah[ks][1], ah[ks][2], ah[ks][3], bv0.y, bv1.y);
                }
            }
        }
        __syncthreads();

        float* st = (float*)(smem + (cur ? K2_A1 : K2_A0));
        {
            const int rA = mt * 16 + lq;
            #pragma unroll
            for (int ch = 0; ch < 5; ch++) {
                #pragma unroll
                for (int q = 0; q < 2; q++) {
                    const int n0 = (nh * 2 + q) * 8 + np;
                    const int col = 5 * n0 + ch;
                    st[rA * K2_AST + col]           = C[ch][q][0];
                    st[rA * K2_AST + col + 5]       = C[ch][q][1];
                    st[(rA + 8) * K2_AST + col]     = C[ch][q][2];
                    st[(rA + 8) * K2_AST + col + 5] = C[ch][q][3];
                }
            }
        }
        __syncthreads();

        #pragma unroll
        for (int it = 0; it < 10; it++) {
            int i = tid + it * 256;
            int r = i / 40, c4 = (i - r * 40) * 4;
            float4 v = *(const float4*)(st + r * K2_AST + c4);
            *(float4*)(out + (size_t)(row0 + r) * LDIM + 320 + c4) = v;
        }
        __syncthreads();
        cur ^= 1;
    }
}

// ============================================================================

extern "C" void kernel_launch(void* const* d_in, const int* in_sizes, int n_in,
                              void* d_out, int out_size)
{
    const float* x  = (const float*)d_in[0];
    const float* w0 = (const float*)d_in[1];
    const float* w1 = (const float*)d_in[2];
    const float* w2 = (const float*)d_in[3];
    const float* b0 = (const float*)d_in[4];
    float* out = (float*)d_out;

    cudaFuncSetAttribute(k0_mma, cudaFuncAttributeMaxDynamicSharedMemorySize, K0_SMEM);
    cudaFuncSetAttribute(k1_mma, cudaFuncAttributeMaxDynamicSharedMemorySize, K1_SMEM);
    cudaFuncSetAttribute(k2_mma, cudaFuncAttributeMaxDynamicSharedMemorySize, K2_SMEM);

    k0_mma<<<152, 512, K0_SMEM>>>(x, w0, b0, out);
    k1_mma<<<152, 512, K1_SMEM>>>(x, w1, out);
    k2_mma<<<304, 256, K2_SMEM>>>(x, w2, out);
}

// round 14
// speedup vs baseline: 1.1467x; 1.1467x over previous
#include <cuda_runtime.h>
#include <cuda_bf16.h>
#include <cstdint>

#define NROWS 200000
#define NTILES 3125          // 200000 / 64 (k1/k2)
#define BM 64
#define LDIM 480

// ============================ HMMA helpers ============================
__device__ __forceinline__ void mma_bf16(float& c0, float& c1, float& c2, float& c3,
                                         uint32_t a0, uint32_t a1, uint32_t a2, uint32_t a3,
                                         uint32_t b0, uint32_t b1)
{
    asm volatile("mma.sync.aligned.m16n8k16.row.col.f32.bf16.bf16.f32 "
                 "{%0,%1,%2,%3}, {%4,%5,%6,%7}, {%8,%9}, {%0,%1,%2,%3};"
                 : "+f"(c0), "+f"(c1), "+f"(c2), "+f"(c3)
                 : "r"(a0), "r"(a1), "r"(a2), "r"(a3), "r"(b0), "r"(b1));
}

__device__ __forceinline__ uint32_t pack_hi(float x, float y, float& rx, float& ry) {
    __nv_bfloat162 h = __float22bfloat162_rn(make_float2(x, y));
    float2 hf = __bfloat1622float2(h);
    rx = x - hf.x; ry = y - hf.y;
    return *(uint32_t*)&h;
}
__device__ __forceinline__ uint32_t pack_lo(float rx, float ry) {
    __nv_bfloat162 l = __float22bfloat162_rn(make_float2(rx, ry));
    return *(uint32_t*)&l;
}
__device__ __forceinline__ void split_bf16(float v, __nv_bfloat16& h, __nv_bfloat16& l) {
    h = __float2bfloat16(v);
    l = __float2bfloat16(v - __bfloat162float(h));
}
__device__ __forceinline__ void split4(const float* f, uint2& hi, uint2& lo) {
    float r0, r1, r2, r3;
    uint32_t h0 = pack_hi(f[0], f[1], r0, r1);
    uint32_t h1 = pack_hi(f[2], f[3], r2, r3);
    hi = make_uint2(h0, h1);
    lo = make_uint2(pack_lo(r0, r1), pack_lo(r2, r3));
}

__device__ __forceinline__ void cp_async16(uint32_t dst, const void* src, bool pred) {
    int sz = pred ? 16 : 0;
    asm volatile("cp.async.cg.shared.global [%0], [%1], 16, %2;"
                 :: "r"(dst), "l"(src), "r"(sz) : "memory");
}
#define CP_COMMIT()  asm volatile("cp.async.commit_group;" ::: "memory")
#define CP_WAIT(n)   asm volatile("cp.async.wait_group %0;" :: "n"(n) : "memory")

// ============================================================================
// Kernel 0 (R10 + ks-loop software pipeline): out[:, 0:128]
// ============================================================================
#define T0_TILES 1563
#define BM0 128
#define K0_AST 136
#define K0_B0   0
#define K0_BIL  512
#define K0_BROW 68
#define K0_A0   70144
#define K0_A1   139776
#define K0_SMEM 209408

__global__ void __launch_bounds__(512, 1)
k0_mma(const float* __restrict__ x, const float* __restrict__ w0,
       const float* __restrict__ b0, float* __restrict__ out)
{
    extern __shared__ char smem[];
    float* b0s = (float*)(smem + K0_B0);
    uint2* bil = (uint2*)(smem + K0_BIL);

    const int tid  = threadIdx.x;
    const int wid  = tid >> 5;
    const int lane = tid & 31;
    const float a0 = 0.08838834764831845f;

    for (int idx = tid; idx < 128 * 64; idx += 512) {
        int n = idx & 127, kp = idx >> 7;
        float v0 = a0 * w0[(2 * kp) * 128 + n];
        float v1 = a0 * w0[(2 * kp + 1) * 128 + n];
        float r0, r1;
        uint32_t hi = pack_hi(v0, v1, r0, r1);
        uint32_t lo = pack_lo(r0, r1);
        bil[n * K0_BROW + kp] = make_uint2(hi, lo);
    }
    if (tid < 128) b0s[tid] = b0[tid];
    __syncthreads();

    const int mh = wid >> 2;
    const int ns = wid & 3;
    const int lq = lane >> 2;
    const int kq = lane & 3;
    const int ak = kq * 2;

    const uint32_t abase0 = (uint32_t)__cvta_generic_to_shared(smem + K0_A0);
    const uint32_t abase1 = (uint32_t)__cvta_generic_to_shared(smem + K0_A1);

    int t = blockIdx.x;
    if (t < T0_TILES) {
        const int row0 = t * BM0;
        #pragma unroll
        for (int it = 0; it < 8; it++) {
            int i = tid + it * 512;
            int r = i >> 5, c4 = (i & 31) << 2;
            int grow = row0 + r;
            bool p = grow < NROWS;
            const float* src = x + (size_t)(p ? grow : 0) * LDIM + c4;
            cp_async16(abase0 + (uint32_t)(r * K0_AST + c4) * 4u, src, p);
        }
        CP_COMMIT();
    }

    int cur = 0;
    for (; t < T0_TILES; t += gridDim.x) {
        const int row0 = t * BM0;
        const int tn = t + gridDim.x;

        if (tn < T0_TILES) {
            const int nrow0 = tn * BM0;
            const uint32_t nb = cur ? abase0 : abase1;
            #pragma unroll
            for (int it = 0; it < 8; it++) {
                int i = tid + it * 512;
                int r = i >> 5, c4 = (i & 31) << 2;
                int grow = nrow0 + r;
                bool p = grow < NROWS;
                const float* src = x + (size_t)(p ? grow : 0) * LDIM + c4;
                cp_async16(nb + (uint32_t)(r * K0_AST + c4) * 4u, src, p);
            }
            CP_COMMIT();
            CP_WAIT(1);
        } else {
            CP_WAIT(0);
        }
        __syncthreads();

        const float* A = (const float*)(smem + (cur ? K0_A1 : K0_A0));

        float C[2][4][4];
        #pragma unroll
        for (int nt = 0; nt < 4; nt++) {
            float bias0 = b0s[ns * 32 + nt * 8 + ak];
            float bias1 = b0s[ns * 32 + nt * 8 + ak + 1];
            #pragma unroll
            for (int mt = 0; mt < 2; mt++) {
                C[mt][nt][0] = bias0; C[mt][nt][1] = bias1;
                C[mt][nt][2] = bias0; C[mt][nt][3] = bias1;
            }
        }

        // software pipeline: raw A floats for ks+1 loaded while ks MMAs issue
        float2 fr[2][4];
        #pragma unroll
        for (int mt = 0; mt < 2; mt++) {
            const int ar = mh * 32 + mt * 16 + lq;
            const float* ap = A + ar * K0_AST + ak;
            fr[mt][0] = *(const float2*)(ap);
            fr[mt][1] = *(const float2*)(ap + 8 * K0_AST);
            fr[mt][2] = *(const float2*)(ap + 8);
            fr[mt][3] = *(const float2*)(ap + 8 * K0_AST + 8);
        }

        #pragma unroll
        for (int ks = 0; ks < 8; ks++) {
            // convert current raw values to bf16 hi/lo fragments
            uint32_t ah[2][4], al[2][4];
            #pragma unroll
            for (int mt = 0; mt < 2; mt++) {
                float rx, ry;
                ah[mt][0] = pack_hi(fr[mt][0].x, fr[mt][0].y, rx, ry); al[mt][0] = pack_lo(rx, ry);
                ah[mt][1] = pack_hi(fr[mt][1].x, fr[mt][1].y, rx, ry); al[mt][1] = pack_lo(rx, ry);
                ah[mt][2] = pack_hi(fr[mt][2].x, fr[mt][2].y, rx, ry); al[mt][2] = pack_lo(rx, ry);
                ah[mt][3] = pack_hi(fr[mt][3].x, fr[mt][3].y, rx, ry); al[mt][3] = pack_lo(rx, ry);
            }
            // issue next ks' raw loads (latency hidden under the 12 MMAs below)
            if (ks < 7) {
                #pragma unroll
                for (int mt = 0; mt < 2; mt++) {
                    const int ar = mh * 32 + mt * 16 + lq;
                    const float* ap = A + ar * K0_AST + ak + (ks + 1) * 16;
                    fr[mt][0] = *(const float2*)(ap);
                    fr[mt][1] = *(const float2*)(ap + 8 * K0_AST);
                    fr[mt][2] = *(const float2*)(ap + 8);
                    fr[mt][3] = *(const float2*)(ap + 8 * K0_AST + 8);
                }
            }

            const int kpb = ks * 8 + kq;
            #pragma unroll
            for (int nt = 0; nt < 4; nt++) {
                const uint2* brow = bil + (ns * 32 + nt * 8 + lq) * K0_BROW;
                uint2 bv0 = brow[kpb];
                uint2 bv1 = brow[kpb + 4];
                #pragma unroll
                for (int mt = 0; mt < 2; mt++) {
                    mma_bf16(C[mt][nt][0], C[mt][nt][1], C[mt][nt][2], C[mt][nt][3],
                             ah[mt][0], ah[mt][1], ah[mt][2], ah[mt][3], bv0.x, bv1.x);
                    mma_bf16(C[mt][nt][0], C[mt][nt][1], C[mt][nt][2], C[mt][nt][3],
                             al[mt][0], al[mt][1], al[mt][2], al[mt][3], bv0.x, bv1.x);
                    mma_bf16(C[mt][nt][0], C[mt][nt][1], C[mt][nt][2], C[mt][nt][3],
                             ah[mt][0], ah[mt][1], ah[mt][2], ah[mt][3], bv0.y, bv1.y);
                }
            }
        }

        #pragma unroll
        for (int mt = 0; mt < 2; mt++) {
            const int grow = row0 + mh * 32 + mt * 16 + lq;
            #pragma unroll
            for (int nt = 0; nt < 4; nt++) {
                float* o0 = out + (size_t)grow * LDIM + ns * 32 + nt * 8 + ak;
                if (grow < NROWS)
                    *(float2*)o0 = make_float2(C[mt][nt][0], C[mt][nt][1]);
                if (grow + 8 < NROWS)
                    *(float2*)(o0 + 8 * LDIM) = make_float2(C[mt][nt][2], C[mt][nt][3]);
            }
        }
        __syncthreads();
        cur ^= 1;
    }
}

// ============================================================================
// Kernel 1 (R6/R10 passing version, reverted): out[:, 128+3w+i]
// ============================================================================
#define K1_ST 72
#define K1_BH 0
#define K1_BL 9216
#define K1_AH 18432
#define K1_AL 46080
#define K1_ABLK 9216
#define K1_OUT 18432
#define K1_OST 196
#define K1_SMEM 73728

__global__ void __launch_bounds__(256, 2)
k1_mma(const float* __restrict__ x, const float* __restrict__ w1,
       float* __restrict__ out)
{
    extern __shared__ char smem[];
    const int tid  = threadIdx.x;
    const int wid  = tid >> 5;
    const int lane = tid & 31;
    const float a1 = 0.125f;

    for (int idx = tid; idx < 64 * 64; idx += 256) {
        int u = idx >> 6, w = idx & 63;
        float v = a1 * w1[idx];
        __nv_bfloat16 h, l;
        split_bf16(v, h, l);
        *(__nv_bfloat16*)(smem + K1_BH + (w * K1_ST + u) * 2) = h;
        *(__nv_bfloat16*)(smem + K1_BL + (w * K1_ST + u) * 2) = l;
    }

    const int mt = wid >> 1;
    const int nh = wid & 1;
    const int ar = mt * 16 + (lane >> 2);
    const int ak = (lane & 3) * 2;
    const int bn = lane >> 2;
    const int np = (lane & 3) * 2;

    for (int t = blockIdx.x; t < NTILES; t += gridDim.x) {
        const int row0 = t * BM;
        __syncthreads();

        #pragma unroll
        for (int it = 0; it < 4; it++) {
            int i = tid + it * 256;
            int r = i >> 4, g = i & 15;
            const float* xp = x + (size_t)(row0 + r) * LDIM + 128 + g * 12;
            float f[12];
            *(float4*)(f)     = *(const float4*)(xp);
            *(float4*)(f + 4) = *(const float4*)(xp + 4);
            *(float4*)(f + 8) = *(const float4*)(xp + 8);
            #pragma unroll
            for (int ch = 0; ch < 3; ch++) {
                float g4[4] = {f[ch], f[ch + 3], f[ch + 6], f[ch + 9]};
                uint2 hi, lo;
                split4(g4, hi, lo);
                uint32_t o = (uint32_t)(ch * K1_ABLK) + (uint32_t)(r * K1_ST + 4 * g) * 2u;
                *(uint2*)(smem + K1_AH + o) = hi;
                *(uint2*)(smem + K1_AL + o) = lo;
            }
        }
        __syncthreads();

        float C[3][4][4];
        #pragma unroll
        for (int ch = 0; ch < 3; ch++) {
            const uint32_t abase = (uint32_t)(ch * K1_ABLK) + (uint32_t)(ar * K1_ST + ak) * 2u;
            uint32_t ah[4][4], al[4][4];
            #pragma unroll
            for (int ks = 0; ks < 4; ks++) {
                uint32_t o = abase + (uint32_t)(ks * 16) * 2u;
                ah[ks][0] = *(const uint32_t*)(smem + K1_AH + o);
                ah[ks][1] = *(const uint32_t*)(smem + K1_AH + o + 8 * K1_ST * 2);
                ah[ks][2] = *(const uint32_t*)(smem + K1_AH + o + 16);
                ah[ks][3] = *(const uint32_t*)(smem + K1_AH + o + 8 * K1_ST * 2 + 16);
                al[ks][0] = *(const uint32_t*)(smem + K1_AL + o);
                al[ks][1] = *(const uint32_t*)(smem + K1_AL + o + 8 * K1_ST * 2);
                al[ks][2] = *(const uint32_t*)(smem + K1_AL + o + 16);
                al[ks][3] = *(const uint32_t*)(smem + K1_AL + o + 8 * K1_ST * 2 + 16);
            }
            #pragma unroll
            for (int q = 0; q < 4; q++) {
                const int nt = nh * 4 + q;
                float p0 = 0.f, p1 = 0.f, p2 = 0.f, p3 = 0.f;
                float q0 = 0.f, q1 = 0.f, q2 = 0.f, q3 = 0.f;
                float s0 = 0.f, s1 = 0.f, s2 = 0.f, s3 = 0.f;
                const uint32_t bbase = (uint32_t)((bn + nt * 8) * K1_ST + ak) * 2u;
                #pragma unroll
                for (int ks = 0; ks < 4; ks++) {
                    uint32_t o = bbase + (uint32_t)(ks * 16) * 2u;
                    uint32_t bh0 = *(const uint32_t*)(smem + K1_BH + o);
                    uint32_t bh1 = *(const uint32_t*)(smem + K1_BH + o + 16);
                    uint32_t bl0 = *(const uint32_t*)(smem + K1_BL + o);
                    uint32_t bl1 = *(const uint32_t*)(smem + K1_BL + o + 16);
                    mma_bf16(p0, p1, p2, p3, ah[ks][0], ah[ks][1], ah[ks][2], ah[ks][3], bh0, bh1);
                    mma_bf16(q0, q1, q2, q3, al[ks][0], al[ks][1], al[ks][2], al[ks][3], bh0, bh1);
                    mma_bf16(s0, s1, s2, s3, ah[ks][0], ah[ks][1], ah[ks][2], ah[ks][3], bl0, bl1);
                }
                C[ch][q][0] = p0 + q0 + s0;
                C[ch][q][1] = p1 + q1 + s1;
                C[ch][q][2] = p2 + q2 + s2;
                C[ch][q][3] = p3 + q3 + s3;
            }
        }
        __syncthreads();

        {
            float* st = (float*)(smem + K1_OUT);
            const int rA = mt * 16 + (lane >> 2);
            #pragma unroll
            for (int ch = 0; ch < 3; ch++) {
                #pragma unroll
                for (int q = 0; q < 4; q++) {
                    const int n0 = (nh * 4 + q) * 8 + np;
                    const int col = 3 * n0 + ch;
                    st[rA * K1_OST + col]           = C[ch][q][0];
                    st[rA * K1_OST + col + 3]       = C[ch][q][1];
                    st[(rA + 8) * K1_OST + col]     = C[ch][q][2];
                    st[(rA + 8) * K1_OST + col + 3] = C[ch][q][3];
                }
            }
        }
        __syncthreads();

        {
            const float* st = (const float*)(smem + K1_OUT);
            #pragma unroll
            for (int it = 0; it < 12; it++) {
                int i = tid + it * 256;
                int r = i / 48, c4 = (i - r * 48) * 4;
                float4 v = *(const float4*)(st + r * K1_OST + c4);
                *(float4*)(out + (size_t)(row0 + r) * LDIM + 128 + c4) = v;
            }
        }
    }
}

// ============================================================================
// Kernel 2 (R6/R10 passing version, reverted): out[:, 320+5w+i]
// ============================================================================
#define K2_ST 40
#define K2_BH 0
#define K2_BL 2560
#define K2_AH 5120
#define K2_AL 30720
#define K2_ABLK 5120
#define K2_OUT 56320
#define K2_OST 164
#define K2_SMEM 98304

__global__ void __launch_bounds__(256, 2)
k2_mma(const float* __restrict__ x, const float* __restrict__ w2,
       float* __restrict__ out)
{
    extern __shared__ char smem[];
    const int tid  = threadIdx.x;
    const int wid  = tid >> 5;
    const int lane = tid & 31;
    const float a2 = 0.17677669529663687f;

    for (int idx = tid; idx < 32 * 32; idx += 256) {
        int u = idx >> 5, w = idx & 31;
        float v = a2 * w2[idx];
        __nv_bfloat16 h, l;
        split_bf16(v, h, l);
        *(__nv_bfloat16*)(smem + K2_BH + (w * K2_ST + u) * 2) = h;
        *(__nv_bfloat16*)(smem + K2_BL + (w * K2_ST + u) * 2) = l;
    }

    const int mt = wid >> 1;
    const int nh = wid & 1;
    const int ar = mt * 16 + (lane >> 2);
    const int ak = (lane & 3) * 2;
    const int bn = lane >> 2;
    const int np = (lane & 3) * 2;
    float* st = (float*)(smem + K2_OUT);

    for (int t = blockIdx.x; t < NTILES; t += gridDim.x) {
        const int row0 = t * BM;
        __syncthreads();

        #pragma unroll
        for (int it = 0; it < 2; it++) {
            int i = tid + it * 256;
            int r = i >> 3, g = i & 7;
            const float* xp = x + (size_t)(row0 + r) * LDIM + 320 + g * 20;
            float f[20];
            #pragma unroll
            for (int q = 0; q < 5; q++)
                *(float4*)(f + 4 * q) = *(const float4*)(xp + 4 * q);
            #pragma unroll
            for (int ch = 0; ch < 5; ch++) {
                float g4[4] = {f[ch], f[ch + 5], f[ch + 10], f[ch + 15]};
                uint2 hi, lo;
                split4(g4, hi, lo);
                uint32_t o = (uint32_t)(ch * K2_ABLK) + (uint32_t)(r * K2_ST + 4 * g) * 2u;
                *(uint2*)(smem + K2_AH + o) = hi;
                *(uint2*)(smem + K2_AL + o) = lo;
            }
        }
        __syncthreads();

        const int rA = mt * 16 + (lane >> 2);
        #pragma unroll
        for (int ch = 0; ch < 5; ch++) {
            const uint32_t abase = (uint32_t)(ch * K2_ABLK) + (uint32_t)(ar * K2_ST + ak) * 2u;
            uint32_t ah[2][4], al[2][4];
            #pragma unroll
            for (int ks = 0; ks < 2; ks++) {
                uint32_t o = abase + (uint32_t)(ks * 16) * 2u;
                ah[ks][0] = *(const uint32_t*)(smem + K2_AH + o);
                ah[ks][1] = *(const uint32_t*)(smem + K2_AH + o + 8 * K2_ST * 2);
                ah[ks][2] = *(const uint32_t*)(smem + K2_AH + o + 16);
                ah[ks][3] = *(const uint32_t*)(smem + K2_AH + o + 8 * K2_ST * 2 + 16);
                al[ks][0] = *(const uint32_t*)(smem + K2_AL + o);
                al[ks][1] = *(const uint32_t*)(smem + K2_AL + o + 8 * K2_ST * 2);
                al[ks][2] = *(const uint32_t*)(smem + K2_AL + o + 16);
                al[ks][3] = *(const uint32_t*)(smem + K2_AL + o + 8 * K2_ST * 2 + 16);
            }
            #pragma unroll
            for (int q = 0; q < 2; q++) {
                const int nt = nh * 2 + q;
                float p0 = 0.f, p1 = 0.f, p2 = 0.f, p3 = 0.f;
                float q0 = 0.f, q1 = 0.f, q2 = 0.f, q3 = 0.f;
                float s0 = 0.f, s1 = 0.f, s2 = 0.f, s3 = 0.f;
                const uint32_t bbase = (uint32_t)((bn + nt * 8) * K2_ST + ak) * 2u;
                #pragma unroll
                for (int ks = 0; ks < 2; ks++) {
                    uint32_t o = bbase + (uint32_t)(ks * 16) * 2u;
                    uint32_t bh0 = *(const uint32_t*)(smem + K2_BH + o);
                    uint32_t bh1 = *(const uint32_t*)(smem + K2_BH + o + 16);
                    uint32_t bl0 = *(const uint32_t*)(smem + K2_BL + o);
                    uint32_t bl1 = *(const uint32_t*)(smem + K2_BL + o + 16);
                    mma_bf16(p0, p1, p2, p3, ah[ks][0], ah[ks][1], ah[ks][2], ah[ks][3], bh0, bh1);
                    mma_bf16(q0, q1, q2, q3, al[ks][0], al[ks][1], al[ks][2], al[ks][3], bh0, bh1);
                    mma_bf16(s0, s1, s2, s3, ah[ks][0], ah[ks][1], ah[ks][2], ah[ks][3], bl0, bl1);
                }
                const int n0 = nt * 8 + np;
                const int col = 5 * n0 + ch;
                st[rA * K2_OST + col]           = p0 + q0 + s0;
                st[rA * K2_OST + col + 5]       = p1 + q1 + s1;
                st[(rA + 8) * K2_OST + col]     = p2 + q2 + s2;
                st[(rA + 8) * K2_OST + col + 5] = p3 + q3 + s3;
            }
        }
        __syncthreads();

        #pragma unroll
        for (int it = 0; it < 10; it++) {
            int i = tid + it * 256;
            int r = i / 40, c4 = (i - r * 40) * 4;
            float4 v = *(const float4*)(st + r * K2_OST + c4);
            *(float4*)(out + (size_t)(row0 + r) * LDIM + 320 + c4) = v;
        }
    }
}

// ============================================================================

extern "C" void kernel_launch(void* const* d_in, const int* in_sizes, int n_in,
                              void* d_out, int out_size)
{
    const float* x  = (const float*)d_in[0];
    const float* w0 = (const float*)d_in[1];
    const float* w1 = (const float*)d_in[2];
    const float* w2 = (const float*)d_in[3];
    const float* b0 = (const float*)d_in[4];
    float* out = (float*)d_out;

    cudaFuncSetAttribute(k0_mma, cudaFuncAttributeMaxDynamicSharedMemorySize, K0_SMEM);
    cudaFuncSetAttribute(k1_mma, cudaFuncAttributeMaxDynamicSharedMemorySize, K1_SMEM);
    cudaFuncSetAttribute(k2_mma, cudaFuncAttributeMaxDynamicSharedMemorySize, K2_SMEM);

    k0_mma<<<152, 512, K0_SMEM>>>(x, w0, b0, out);
    k1_mma<<<304, 256, K1_SMEM>>>(x, w1, out);
    k2_mma<<<304, 256, K2_SMEM>>>(x, w2, out);
}

// round 15
// speedup vs baseline: 1.5752x; 1.3737x over previous
#include <cuda_runtime.h>
#include <cuda_fp16.h>
#include <cstdint>

#define NROWS 200000
#define NTILES 3125          // 200000 / 64
#define BM 64
#define LDIM 480

// ============================ HMMA helpers ============================
__device__ __forceinline__ void mma_f16(float& c0, float& c1, float& c2, float& c3,
                                        uint32_t a0, uint32_t a1, uint32_t a2, uint32_t a3,
                                        uint32_t b0, uint32_t b1)
{
    asm volatile("mma.sync.aligned.m16n8k16.row.col.f32.f16.f16.f32 "
                 "{%0,%1,%2,%3}, {%4,%5,%6,%7}, {%8,%9}, {%0,%1,%2,%3};"
                 : "+f"(c0), "+f"(c1), "+f"(c2), "+f"(c3)
                 : "r"(a0), "r"(a1), "r"(a2), "r"(a3), "r"(b0), "r"(b1));
}

__device__ __forceinline__ uint32_t pack_h2(float x, float y) {
    __half2 h = __float22half2_rn(make_float2(x, y));
    return *(uint32_t*)&h;
}

// ============================================================================
// Kernel 0 (fp16 single-pass): out[:, 0:128] = x[:,0:128] @ (a0*w0) + b0
// 256 thr, 2 CTAs/SM, BM=64. 8 warps = 2 m-halves x 4 n-strips (32x32).
// smem: b0s[0,512) Bs fp16[512,35328+512=35840) As fp16[35840,53248)
// fp16 row stride 136 -> frag lds bank (4*lq+kq) mod 32: conflict-free.
// ============================================================================
#define K0_ST 136
#define K0_B0 0
#define K0_BS 512
#define K0_AS 35840
#define K0_SMEM 53248

__global__ void __launch_bounds__(256, 2)
k0_mma(const float* __restrict__ x, const float* __restrict__ w0,
       const float* __restrict__ b0, float* __restrict__ out)
{
    extern __shared__ char smem[];
    float* b0s = (float*)(smem + K0_B0);

    const int tid  = threadIdx.x;
    const int wid  = tid >> 5;
    const int lane = tid & 31;
    const float a0 = 0.08838834764831845f;   // 1/sqrt(128)

    // stage B: B[n][k] = a0 * w0[k][n], fp16
    for (int idx = tid; idx < 128 * 128; idx += 256) {
        int n = idx & 127, k = idx >> 7;
        __half v = __float2half_rn(a0 * w0[k * 128 + n]);
        *(__half*)(smem + K0_BS + (n * K0_ST + k) * 2) = v;
    }
    if (tid < 128) b0s[tid] = b0[tid];

    const int mh = wid >> 2;       // 0..1
    const int ns = wid & 3;        // 0..3
    const int lq = lane >> 2;
    const int kq = lane & 3;
    const int ak = kq * 2;

    __syncthreads();

    for (int t = blockIdx.x; t < NTILES; t += gridDim.x) {
        const int row0 = t * BM;

        // stage A: 64 rows x 128 cols fp32 -> fp16 (float4 loads, uint2 stores)
        #pragma unroll
        for (int it = 0; it < 8; it++) {
            int i = tid + it * 256;
            int r = i >> 5, c4 = (i & 31) << 2;
            float4 v = *(const float4*)(x + (size_t)(row0 + r) * LDIM + c4);
            uint2 p = make_uint2(pack_h2(v.x, v.y), pack_h2(v.z, v.w));
            *(uint2*)(smem + K0_AS + (uint32_t)(r * K0_ST + c4) * 2u) = p;
        }
        __syncthreads();

        float C[2][4][4];
        #pragma unroll
        for (int nt = 0; nt < 4; nt++) {
            float bias0 = b0s[ns * 32 + nt * 8 + ak];
            float bias1 = b0s[ns * 32 + nt * 8 + ak + 1];
            #pragma unroll
            for (int mt = 0; mt < 2; mt++) {
                C[mt][nt][0] = bias0; C[mt][nt][1] = bias1;
                C[mt][nt][2] = bias0; C[mt][nt][3] = bias1;
            }
        }

        #pragma unroll
        for (int ks = 0; ks < 8; ks++) {
            const int k = ks * 16 + ak;
            uint32_t a[2][4];
            #pragma unroll
            for (int mt = 0; mt < 2; mt++) {
                const int ar = mh * 32 + mt * 16 + lq;
                const char* ap = smem + K0_AS + (uint32_t)(ar * K0_ST + k) * 2u;
                a[mt][0] = *(const uint32_t*)(ap);
                a[mt][1] = *(const uint32_t*)(ap + 8 * K0_ST * 2);
                a[mt][2] = *(const uint32_t*)(ap + 16);
                a[mt][3] = *(const uint32_t*)(ap + 8 * K0_ST * 2 + 16);
            }
            #pragma unroll
            for (int nt = 0; nt < 4; nt++) {
                const int bn = ns * 32 + nt * 8 + lq;
                const char* bp = smem + K0_BS + (uint32_t)(bn * K0_ST + k) * 2u;
                uint32_t bv0 = *(const uint32_t*)(bp);
                uint32_t bv1 = *(const uint32_t*)(bp + 16);
                #pragma unroll
                for (int mt = 0; mt < 2; mt++)
                    mma_f16(C[mt][nt][0], C[mt][nt][1], C[mt][nt][2], C[mt][nt][3],
                            a[mt][0], a[mt][1], a[mt][2], a[mt][3], bv0, bv1);
            }
        }

        #pragma unroll
        for (int mt = 0; mt < 2; mt++) {
            const int grow = row0 + mh * 32 + mt * 16 + lq;
            #pragma unroll
            for (int nt = 0; nt < 4; nt++) {
                float* o0 = out + (size_t)grow * LDIM + ns * 32 + nt * 8 + ak;
                *(float2*)o0              = make_float2(C[mt][nt][0], C[mt][nt][1]);
                *(float2*)(o0 + 8 * LDIM) = make_float2(C[mt][nt][2], C[mt][nt][3]);
            }
        }
        __syncthreads();
    }
}

// ============================================================================
// Kernel 1 (fp16 single-pass): out[:, 128+3w+i], i=0..2
// 256 thr, 2 CTAs/SM. 8 warps = 4 m-tiles x 2 n-halves.
// smem: Bs[0,9216) As[9216,36864) (3ch x 64x72 fp16) OUT[36864,87040)
// ============================================================================
#define K1_ST 72
#define K1_BS 0
#define K1_AS 9216
#define K1_ABLK 9216
#define K1_OUT 36864
#define K1_OST 196
#define K1_SMEM 87040

__global__ void __launch_bounds__(256, 2)
k1_mma(const float* __restrict__ x, const float* __restrict__ w1,
       float* __restrict__ out)
{
    extern __shared__ char smem[];
    const int tid  = threadIdx.x;
    const int wid  = tid >> 5;
    const int lane = tid & 31;
    const float a1 = 0.125f;   // 1/sqrt(64)

    // B[n=w][k=u] fp16
    for (int idx = tid; idx < 64 * 64; idx += 256) {
        int u = idx >> 6, w = idx & 63;
        *(__half*)(smem + K1_BS + (w * K1_ST + u) * 2) = __float2half_rn(a1 * w1[idx]);
    }

    const int mt = wid >> 1;       // 0..3
    const int nh = wid & 1;        // 0..1
    const int lq = lane >> 2;
    const int kq = lane & 3;
    const int ak = kq * 2;
    const int np = (lane & 3) * 2;

    for (int t = blockIdx.x; t < NTILES; t += gridDim.x) {
        const int row0 = t * BM;
        __syncthreads();   // prior readout done before staging overwrites

        // stage A: channel-deinterleave -> 3 x [64][64] fp16 (stride 72)
        #pragma unroll
        for (int it = 0; it < 4; it++) {
            int i = tid + it * 256;
            int r = i >> 4, g = i & 15;
            const float* xp = x + (size_t)(row0 + r) * LDIM + 128 + g * 12;
            float f[12];
            *(float4*)(f)     = *(const float4*)(xp);
            *(float4*)(f + 4) = *(const float4*)(xp + 4);
            *(float4*)(f + 8) = *(const float4*)(xp + 8);
            #pragma unroll
            for (int ch = 0; ch < 3; ch++) {
                uint2 p = make_uint2(pack_h2(f[ch], f[ch + 3]),
                                     pack_h2(f[ch + 6], f[ch + 9]));
                *(uint2*)(smem + K1_AS + ch * K1_ABLK
                          + (uint32_t)(r * K1_ST + 4 * g) * 2u) = p;
            }
        }
        __syncthreads();

        float C[3][4][4];
        #pragma unroll
        for (int ch = 0; ch < 3; ch++) {
            const char* Ab = smem + K1_AS + ch * K1_ABLK;
            uint32_t a[4][4];
            #pragma unroll
            for (int ks = 0; ks < 4; ks++) {
                const char* ap = Ab + (uint32_t)((mt * 16 + lq) * K1_ST + ks * 16 + ak) * 2u;
                a[ks][0] = *(const uint32_t*)(ap);
                a[ks][1] = *(const uint32_t*)(ap + 8 * K1_ST * 2);
                a[ks][2] = *(const uint32_t*)(ap + 16);
                a[ks][3] = *(const uint32_t*)(ap + 8 * K1_ST * 2 + 16);
            }
            #pragma unroll
            for (int q = 0; q < 4; q++) {
                const int nt = nh * 4 + q;
                float c0 = 0.f, c1 = 0.f, c2 = 0.f, c3 = 0.f;
                const int bn = nt * 8 + lq;
                #pragma unroll
                for (int ks = 0; ks < 4; ks++) {
                    const char* bp = smem + K1_BS
                                   + (uint32_t)(bn * K1_ST + ks * 16 + ak) * 2u;
                    uint32_t bv0 = *(const uint32_t*)(bp);
                    uint32_t bv1 = *(const uint32_t*)(bp + 16);
                    mma_f16(c0, c1, c2, c3, a[ks][0], a[ks][1], a[ks][2], a[ks][3], bv0, bv1);
                }
                C[ch][q][0] = c0; C[ch][q][1] = c1; C[ch][q][2] = c2; C[ch][q][3] = c3;
            }
        }
        __syncthreads();

        // scatter C -> out-stage, then coalesced store
        float* st = (float*)(smem + K1_OUT);
        {
            const int rA = mt * 16 + lq;
            #pragma unroll
            for (int ch = 0; ch < 3; ch++) {
                #pragma unroll
                for (int q = 0; q < 4; q++) {
                    const int n0 = (nh * 4 + q) * 8 + np;
                    const int col = 3 * n0 + ch;
                    st[rA * K1_OST + col]           = C[ch][q][0];
                    st[rA * K1_OST + col + 3]       = C[ch][q][1];
                    st[(rA + 8) * K1_OST + col]     = C[ch][q][2];
                    st[(rA + 8) * K1_OST + col + 3] = C[ch][q][3];
                }
            }
        }
        __syncthreads();

        #pragma unroll
        for (int it = 0; it < 12; it++) {
            int i = tid + it * 256;
            int r = i / 48, c4 = (i - r * 48) * 4;
            float4 v = *(const float4*)(st + r * K1_OST + c4);
            *(float4*)(out + (size_t)(row0 + r) * LDIM + 128 + c4) = v;
        }
    }
}

// ============================================================================
// Kernel 2 (fp16 single-pass): out[:, 320+5w+i], i=0..4
// 256 thr, 2 CTAs/SM. 8 warps = 4 m-tiles x 2 n-halves.
// smem: Bs[0,2560) As[2560,28160) (5ch x 64x40 fp16) OUT[28160,70144)
// ============================================================================
#define K2_ST 40
#define K2_BS 0
#define K2_AS 2560
#define K2_ABLK 5120
#define K2_OUT 28160
#define K2_OST 164
#define K2_SMEM 70144

__global__ void __launch_bounds__(256, 2)
k2_mma(const float* __restrict__ x, const float* __restrict__ w2,
       float* __restrict__ out)
{
    extern __shared__ char smem[];
    const int tid  = threadIdx.x;
    const int wid  = tid >> 5;
    const int lane = tid & 31;
    const float a2 = 0.17677669529663687f;  // 1/sqrt(32)

    for (int idx = tid; idx < 32 * 32; idx += 256) {
        int u = idx >> 5, w = idx & 31;
        *(__half*)(smem + K2_BS + (w * K2_ST + u) * 2) = __float2half_rn(a2 * w2[idx]);
    }

    const int mt = wid >> 1;
    const int nh = wid & 1;
    const int lq = lane >> 2;
    const int kq = lane & 3;
    const int ak = kq * 2;
    const int np = (lane & 3) * 2;
    float* st = (float*)(smem + K2_OUT);

    for (int t = blockIdx.x; t < NTILES; t += gridDim.x) {
        const int row0 = t * BM;
        __syncthreads();

        // stage A: channel-deinterleave -> 5 x [64][32] fp16 (stride 40)
        #pragma unroll
        for (int it = 0; it < 2; it++) {
            int i = tid + it * 256;
            int r = i >> 3, g = i & 7;
            const float* xp = x + (size_t)(row0 + r) * LDIM + 320 + g * 20;
            float f[20];
            #pragma unroll
            for (int q = 0; q < 5; q++)
                *(float4*)(f + 4 * q) = *(const float4*)(xp + 4 * q);
            #pragma unroll
            for (int ch = 0; ch < 5; ch++) {
                uint2 p = make_uint2(pack_h2(f[ch], f[ch + 5]),
                                     pack_h2(f[ch + 10], f[ch + 15]));
                *(uint2*)(smem + K2_AS + ch * K2_ABLK
                          + (uint32_t)(r * K2_ST + 4 * g) * 2u) = p;
            }
        }
        __syncthreads();

        const int rA = mt * 16 + lq;
        #pragma unroll
        for (int ch = 0; ch < 5; ch++) {
            const char* Ab = smem + K2_AS + ch * K2_ABLK;
            uint32_t a[2][4];
            #pragma unroll
            for (int ks = 0; ks < 2; ks++) {
                const char* ap = Ab + (uint32_t)(rA * K2_ST + ks * 16 + ak) * 2u;
                a[ks][0] = *(const uint32_t*)(ap);
                a[ks][1] = *(const uint32_t*)(ap + 8 * K2_ST * 2);
                a[ks][2] = *(const uint32_t*)(ap + 16);
                a[ks][3] = *(const uint32_t*)(ap + 8 * K2_ST * 2 + 16);
            }
            #pragma unroll
            for (int q = 0; q < 2; q++) {
                const int nt = nh * 2 + q;
                float c0 = 0.f, c1 = 0.f, c2 = 0.f, c3 = 0.f;
                const int bn = nt * 8 + lq;
                #pragma unroll
                for (int ks = 0; ks < 2; ks++) {
                    const char* bp = smem + K2_BS
                                   + (uint32_t)(bn * K2_ST + ks * 16 + ak) * 2u;
                    uint32_t bv0 = *(const uint32_t*)(bp);
                    uint32_t bv1 = *(const uint32_t*)(bp + 16);
                    mma_f16(c0, c1, c2, c3, a[ks][0], a[ks][1], a[ks][2], a[ks][3], bv0, bv1);
                }
                const int n0 = nt * 8 + np;
                const int col = 5 * n0 + ch;
                st[rA * K2_OST + col]           = c0;
                st[rA * K2_OST + col + 5]       = c1;
                st[(rA + 8) * K2_OST + col]     = c2;
                st[(rA + 8) * K2_OST + col + 5] = c3;
            }
        }
        __syncthreads();

        #pragma unroll
        for (int it = 0; it < 10; it++) {
            int i = tid + it * 256;
            int r = i / 40, c4 = (i - r * 40) * 4;
            float4 v = *(const float4*)(st + r * K2_OST + c4);
            *(float4*)(out + (size_t)(row0 + r) * LDIM + 320 + c4) = v;
        }
    }
}

// ============================================================================

extern "C" void kernel_launch(void* const* d_in, const int* in_sizes, int n_in,
                              void* d_out, int out_size)
{
    const float* x  = (const float*)d_in[0];
    const float* w0 = (const float*)d_in[1];
    const float* w1 = (const float*)d_in[2];
    const float* w2 = (const float*)d_in[3];
    const float* b0 = (const float*)d_in[4];
    float* out = (float*)d_out;

    cudaFuncSetAttribute(k0_mma, cudaFuncAttributeMaxDynamicSharedMemorySize, K0_SMEM);
    cudaFuncSetAttribute(k1_mma, cudaFuncAttributeMaxDynamicSharedMemorySize, K1_SMEM);
    cudaFuncSetAttribute(k2_mma, cudaFuncAttributeMaxDynamicSharedMemorySize, K2_SMEM);

    k0_mma<<<304, 256, K0_SMEM>>>(x, w0, b0, out);
    k1_mma<<<304, 256, K1_SMEM>>>(x, w1, out);
    k2_mma<<<304, 256, K2_SMEM>>>(x, w2, out);
}

// round 16
// speedup vs baseline: 1.6012x; 1.0165x over previous
#include <cuda_runtime.h>
#include <cuda_fp16.h>
#include <cstdint>

#define NROWS 200000
#define NTILES 3125          // 200000 / 64
#define BM 64
#define LDIM 480

// ============================ HMMA helpers ============================
__device__ __forceinline__ void mma_f16(float& c0, float& c1, float& c2, float& c3,
                                        uint32_t a0, uint32_t a1, uint32_t a2, uint32_t a3,
                                        uint32_t b0, uint32_t b1)
{
    asm volatile("mma.sync.aligned.m16n8k16.row.col.f32.f16.f16.f32 "
                 "{%0,%1,%2,%3}, {%4,%5,%6,%7}, {%8,%9}, {%0,%1,%2,%3};"
                 : "+f"(c0), "+f"(c1), "+f"(c2), "+f"(c3)
                 : "r"(a0), "r"(a1), "r"(a2), "r"(a3), "r"(b0), "r"(b1));
}

__device__ __forceinline__ uint32_t pack_h2(float x, float y) {
    __half2 h = __float22half2_rn(make_float2(x, y));
    return *(uint32_t*)&h;
}

__device__ __forceinline__ void cp_async16(uint32_t dst, const void* src) {
    asm volatile("cp.async.cg.shared.global [%0], [%1], 16;"
                 :: "r"(dst), "l"(src) : "memory");
}
#define CP_COMMIT()  asm volatile("cp.async.commit_group;" ::: "memory")
#define CP_WAIT(n)   asm volatile("cp.async.wait_group %0;" :: "n"(n) : "memory")

// ============================================================================
// Kernel 0 (fp16 + cp.async double buffer): out[:, 0:128]
// 256 thr, 2 CTAs/SM, BM=64. 8 warps = 2 m-halves x 4 n-strips (32x32).
// A staged fp32 via cp.async (double buffer); fp16 conversion at fragment load
// (contiguous float2 -> one F2FP per fragment).
// smem: b0s[0,512) Bs fp16[512,35328) A0 fp32[35328,70144) A1[70144,104960)
// ============================================================================
#define K0_ST  136           // fp16 B row stride (halves)
#define K0_AST 136           // fp32 A row stride (floats)
#define K0_B0  0
#define K0_BS  512
#define K0_A0  35328
#define K0_A1  70144
#define K0_SMEM 104960

__global__ void __launch_bounds__(256, 2)
k0_mma(const float* __restrict__ x, const float* __restrict__ w0,
       const float* __restrict__ b0, float* __restrict__ out)
{
    extern __shared__ char smem[];
    float* b0s = (float*)(smem + K0_B0);

    const int tid  = threadIdx.x;
    const int wid  = tid >> 5;
    const int lane = tid & 31;
    const float a0 = 0.08838834764831845f;   // 1/sqrt(128)

    // stage B: B[n][k] = a0 * w0[k][n], fp16
    for (int idx = tid; idx < 128 * 128; idx += 256) {
        int n = idx & 127, k = idx >> 7;
        __half v = __float2half_rn(a0 * w0[k * 128 + n]);
        *(__half*)(smem + K0_BS + (n * K0_ST + k) * 2) = v;
    }
    if (tid < 128) b0s[tid] = b0[tid];
    __syncthreads();

    const int mh = wid >> 2;       // 0..1
    const int ns = wid & 3;        // 0..3
    const int lq = lane >> 2;
    const int kq = lane & 3;
    const int ak = kq * 2;

    const uint32_t ab0 = (uint32_t)__cvta_generic_to_shared(smem + K0_A0);
    const uint32_t ab1 = (uint32_t)__cvta_generic_to_shared(smem + K0_A1);

    // prologue: tile t -> buf0 (exact tiling: no tail predicates)
    int t = blockIdx.x;
    if (t < NTILES) {
        const int row0 = t * BM;
        #pragma unroll
        for (int it = 0; it < 8; it++) {
            int i = tid + it * 256;
            int r = i >> 5, c4 = (i & 31) << 2;
            cp_async16(ab0 + (uint32_t)(r * K0_AST + c4) * 4u,
                       x + (size_t)(row0 + r) * LDIM + c4);
        }
        CP_COMMIT();
    }

    int cur = 0;
    for (; t < NTILES; t += gridDim.x) {
        const int row0 = t * BM;
        const int tn = t + gridDim.x;

        if (tn < NTILES) {
            const int nrow0 = tn * BM;
            const uint32_t nb = cur ? ab0 : ab1;
            #pragma unroll
            for (int it = 0; it < 8; it++) {
                int i = tid + it * 256;
                int r = i >> 5, c4 = (i & 31) << 2;
                cp_async16(nb + (uint32_t)(r * K0_AST + c4) * 4u,
                           x + (size_t)(nrow0 + r) * LDIM + c4);
            }
            CP_COMMIT();
            CP_WAIT(1);
        } else {
            CP_WAIT(0);
        }
        __syncthreads();

        const float* A = (const float*)(smem + (cur ? K0_A1 : K0_A0));

        float C[2][4][4];
        #pragma unroll
        for (int nt = 0; nt < 4; nt++) {
            float bias0 = b0s[ns * 32 + nt * 8 + ak];
            float bias1 = b0s[ns * 32 + nt * 8 + ak + 1];
            #pragma unroll
            for (int mt = 0; mt < 2; mt++) {
                C[mt][nt][0] = bias0; C[mt][nt][1] = bias1;
                C[mt][nt][2] = bias0; C[mt][nt][3] = bias1;
            }
        }

        #pragma unroll
        for (int ks = 0; ks < 8; ks++) {
            const int k = ks * 16 + ak;
            uint32_t a[2][4];
            #pragma unroll
            for (int mt = 0; mt < 2; mt++) {
                const int ar = mh * 32 + mt * 16 + lq;
                const float* ap = A + ar * K0_AST + k;
                float2 f0 = *(const float2*)(ap);
                float2 f1 = *(const float2*)(ap + 8 * K0_AST);
                float2 f2 = *(const float2*)(ap + 8);
                float2 f3 = *(const float2*)(ap + 8 * K0_AST + 8);
                a[mt][0] = pack_h2(f0.x, f0.y);
                a[mt][1] = pack_h2(f1.x, f1.y);
                a[mt][2] = pack_h2(f2.x, f2.y);
                a[mt][3] = pack_h2(f3.x, f3.y);
            }
            #pragma unroll
            for (int nt = 0; nt < 4; nt++) {
                const int bn = ns * 32 + nt * 8 + lq;
                const char* bp = smem + K0_BS + (uint32_t)(bn * K0_ST + k) * 2u;
                uint32_t bv0 = *(const uint32_t*)(bp);
                uint32_t bv1 = *(const uint32_t*)(bp + 16);
                #pragma unroll
                for (int mt = 0; mt < 2; mt++)
                    mma_f16(C[mt][nt][0], C[mt][nt][1], C[mt][nt][2], C[mt][nt][3],
                            a[mt][0], a[mt][1], a[mt][2], a[mt][3], bv0, bv1);
            }
        }

        #pragma unroll
        for (int mt = 0; mt < 2; mt++) {
            const int grow = row0 + mh * 32 + mt * 16 + lq;
            #pragma unroll
            for (int nt = 0; nt < 4; nt++) {
                float* o0 = out + (size_t)grow * LDIM + ns * 32 + nt * 8 + ak;
                *(float2*)o0              = make_float2(C[mt][nt][0], C[mt][nt][1]);
                *(float2*)(o0 + 8 * LDIM) = make_float2(C[mt][nt][2], C[mt][nt][3]);
            }
        }
        __syncthreads();
        cur ^= 1;
    }
}

// ============================================================================
// Kernel 1 (fp16 single-pass, unchanged from R15): out[:, 128+3w+i]
// ============================================================================
#define K1_ST 72
#define K1_BS 0
#define K1_AS 9216
#define K1_ABLK 9216
#define K1_OUT 36864
#define K1_OST 196
#define K1_SMEM 87040

__global__ void __launch_bounds__(256, 2)
k1_mma(const float* __restrict__ x, const float* __restrict__ w1,
       float* __restrict__ out)
{
    extern __shared__ char smem[];
    const int tid  = threadIdx.x;
    const int wid  = tid >> 5;
    const int lane = tid & 31;
    const float a1 = 0.125f;   // 1/sqrt(64)

    for (int idx = tid; idx < 64 * 64; idx += 256) {
        int u = idx >> 6, w = idx & 63;
        *(__half*)(smem + K1_BS + (w * K1_ST + u) * 2) = __float2half_rn(a1 * w1[idx]);
    }

    const int mt = wid >> 1;
    const int nh = wid & 1;
    const int lq = lane >> 2;
    const int kq = lane & 3;
    const int ak = kq * 2;
    const int np = (lane & 3) * 2;

    for (int t = blockIdx.x; t < NTILES; t += gridDim.x) {
        const int row0 = t * BM;
        __syncthreads();

        #pragma unroll
        for (int it = 0; it < 4; it++) {
            int i = tid + it * 256;
            int r = i >> 4, g = i & 15;
            const float* xp = x + (size_t)(row0 + r) * LDIM + 128 + g * 12;
            float f[12];
            *(float4*)(f)     = *(const float4*)(xp);
            *(float4*)(f + 4) = *(const float4*)(xp + 4);
            *(float4*)(f + 8) = *(const float4*)(xp + 8);
            #pragma unroll
            for (int ch = 0; ch < 3; ch++) {
                uint2 p = make_uint2(pack_h2(f[ch], f[ch + 3]),
                                     pack_h2(f[ch + 6], f[ch + 9]));
                *(uint2*)(smem + K1_AS + ch * K1_ABLK
                          + (uint32_t)(r * K1_ST + 4 * g) * 2u) = p;
            }
        }
        __syncthreads();

        float C[3][4][4];
        #pragma unroll
        for (int ch = 0; ch < 3; ch++) {
            const char* Ab = smem + K1_AS + ch * K1_ABLK;
            uint32_t a[4][4];
            #pragma unroll
            for (int ks = 0; ks < 4; ks++) {
                const char* ap = Ab + (uint32_t)((mt * 16 + lq) * K1_ST + ks * 16 + ak) * 2u;
                a[ks][0] = *(const uint32_t*)(ap);
                a[ks][1] = *(const uint32_t*)(ap + 8 * K1_ST * 2);
                a[ks][2] = *(const uint32_t*)(ap + 16);
                a[ks][3] = *(const uint32_t*)(ap + 8 * K1_ST * 2 + 16);
            }
            #pragma unroll
            for (int q = 0; q < 4; q++) {
                const int nt = nh * 4 + q;
                float c0 = 0.f, c1 = 0.f, c2 = 0.f, c3 = 0.f;
                const int bn = nt * 8 + lq;
                #pragma unroll
                for (int ks = 0; ks < 4; ks++) {
                    const char* bp = smem + K1_BS
                                   + (uint32_t)(bn * K1_ST + ks * 16 + ak) * 2u;
                    uint32_t bv0 = *(const uint32_t*)(bp);
                    uint32_t bv1 = *(const uint32_t*)(bp + 16);
                    mma_f16(c0, c1, c2, c3, a[ks][0], a[ks][1], a[ks][2], a[ks][3], bv0, bv1);
                }
                C[ch][q][0] = c0; C[ch][q][1] = c1; C[ch][q][2] = c2; C[ch][q][3] = c3;
            }
        }
        __syncthreads();

        float* st = (float*)(smem + K1_OUT);
        {
            const int rA = mt * 16 + lq;
            #pragma unroll
            for (int ch = 0; ch < 3; ch++) {
                #pragma unroll
                for (int q = 0; q < 4; q++) {
                    const int n0 = (nh * 4 + q) * 8 + np;
                    const int col = 3 * n0 + ch;
                    st[rA * K1_OST + col]           = C[ch][q][0];
                    st[rA * K1_OST + col + 3]       = C[ch][q][1];
                    st[(rA + 8) * K1_OST + col]     = C[ch][q][2];
                    st[(rA + 8) * K1_OST + col + 3] = C[ch][q][3];
                }
            }
        }
        __syncthreads();

        #pragma unroll
        for (int it = 0; it < 12; it++) {
            int i = tid + it * 256;
            int r = i / 48, c4 = (i - r * 48) * 4;
            float4 v = *(const float4*)(st + r * K1_OST + c4);
            *(float4*)(out + (size_t)(row0 + r) * LDIM + 128 + c4) = v;
        }
    }
}

// ============================================================================
// Kernel 2 (fp16 single-pass, unchanged from R15): out[:, 320+5w+i]
// ============================================================================
#define K2_ST 40
#define K2_BS 0
#define K2_AS 2560
#define K2_ABLK 5120
#define K2_OUT 28160
#define K2_OST 164
#define K2_SMEM 70144

__global__ void __launch_bounds__(256, 2)
k2_mma(const float* __restrict__ x, const float* __restrict__ w2,
       float* __restrict__ out)
{
    extern __shared__ char smem[];
    const int tid  = threadIdx.x;
    const int wid  = tid >> 5;
    const int lane = tid & 31;
    const float a2 = 0.17677669529663687f;  // 1/sqrt(32)

    for (int idx = tid; idx < 32 * 32; idx += 256) {
        int u = idx >> 5, w = idx & 31;
        *(__half*)(smem + K2_BS + (w * K2_ST + u) * 2) = __float2half_rn(a2 * w2[idx]);
    }

    const int mt = wid >> 1;
    const int nh = wid & 1;
    const int lq = lane >> 2;
    const int kq = lane & 3;
    const int ak = kq * 2;
    const int np = (lane & 3) * 2;
    float* st = (float*)(smem + K2_OUT);

    for (int t = blockIdx.x; t < NTILES; t += gridDim.x) {
        const int row0 = t * BM;
        __syncthreads();

        #pragma unroll
        for (int it = 0; it < 2; it++) {
            int i = tid + it * 256;
            int r = i >> 3, g = i & 7;
            const float* xp = x + (size_t)(row0 + r) * LDIM + 320 + g * 20;
            float f[20];
            #pragma unroll
            for (int q = 0; q < 5; q++)
                *(float4*)(f + 4 * q) = *(const float4*)(xp + 4 * q);
            #pragma unroll
            for (int ch = 0; ch < 5; ch++) {
                uint2 p = make_uint2(pack_h2(f[ch], f[ch + 5]),
                                     pack_h2(f[ch + 10], f[ch + 15]));
                *(uint2*)(smem + K2_AS + ch * K2_ABLK
                          + (uint32_t)(r * K2_ST + 4 * g) * 2u) = p;
            }
        }
        __syncthreads();

        const int rA = mt * 16 + lq;
        #pragma unroll
        for (int ch = 0; ch < 5; ch++) {
            const char* Ab = smem + K2_AS + ch * K2_ABLK;
            uint32_t a[2][4];
            #pragma unroll
            for (int ks = 0; ks < 2; ks++) {
                const char* ap = Ab + (uint32_t)(rA * K2_ST + ks * 16 + ak) * 2u;
                a[ks][0] = *(const uint32_t*)(ap);
                a[ks][1] = *(const uint32_t*)(ap + 8 * K2_ST * 2);
                a[ks][2] = *(const uint32_t*)(ap + 16);
                a[ks][3] = *(const uint32_t*)(ap + 8 * K2_ST * 2 + 16);
            }
            #pragma unroll
            for (int q = 0; q < 2; q++) {
                const int nt = nh * 2 + q;
                float c0 = 0.f, c1 = 0.f, c2 = 0.f, c3 = 0.f;
                const int bn = nt * 8 + lq;
                #pragma unroll
                for (int ks = 0; ks < 2; ks++) {
                    const char* bp = smem + K2_BS
                                   + (uint32_t)(bn * K2_ST + ks * 16 + ak) * 2u;
                    uint32_t bv0 = *(const uint32_t*)(bp);
                    uint32_t bv1 = *(const uint32_t*)(bp + 16);
                    mma_f16(c0, c1, c2, c3, a[ks][0], a[ks][1], a[ks][2], a[ks][3], bv0, bv1);
                }
                const int n0 = nt * 8 + np;
                const int col = 5 * n0 + ch;
                st[rA * K2_OST + col]           = c0;
                st[rA * K2_OST + col + 5]       = c1;
                st[(rA + 8) * K2_OST + col]     = c2;
                st[(rA + 8) * K2_OST + col + 5] = c3;
            }
        }
        __syncthreads();

        #pragma unroll
        for (int it = 0; it < 10; it++) {
            int i = tid + it * 256;
            int r = i / 40, c4 = (i - r * 40) * 4;
            float4 v = *(const float4*)(st + r * K2_OST + c4);
            *(float4*)(out + (size_t)(row0 + r) * LDIM + 320 + c4) = v;
        }
    }
}

// ============================================================================

extern "C" void kernel_launch(void* const* d_in, const int* in_sizes, int n_in,
                              void* d_out, int out_size)
{
    const float* x  = (const float*)d_in[0];
    const float* w0 = (const float*)d_in[1];
    const float* w1 = (const float*)d_in[2];
    const float* w2 = (const float*)d_in[3];
    const float* b0 = (const float*)d_in[4];
    float* out = (float*)d_out;

    cudaFuncSetAttribute(k0_mma, cudaFuncAttributeMaxDynamicSharedMemorySize, K0_SMEM);
    cudaFuncSetAttribute(k1_mma, cudaFuncAttributeMaxDynamicSharedMemorySize, K1_SMEM);
    cudaFuncSetAttribute(k2_mma, cudaFuncAttributeMaxDynamicSharedMemorySize, K2_SMEM);

    k0_mma<<<304, 256, K0_SMEM>>>(x, w0, b0, out);
    k1_mma<<<304, 256, K1_SMEM>>>(x, w1, out);
    k2_mma<<<304, 256, K2_SMEM>>>(x, w2, out);
}

// round 17
// speedup vs baseline: 1.6119x; 1.0067x over previous
#include <cuda_runtime.h>
#include <cuda_fp16.h>
#include <cstdint>

#define NROWS 200000
#define NTILES 3125          // 200000 / 64
#define BM 64
#define LDIM 480

// ============================ HMMA helpers ============================
__device__ __forceinline__ void mma_f16(float& c0, float& c1, float& c2, float& c3,
                                        uint32_t a0, uint32_t a1, uint32_t a2, uint32_t a3,
                                        uint32_t b0, uint32_t b1)
{
    asm volatile("mma.sync.aligned.m16n8k16.row.col.f32.f16.f16.f32 "
                 "{%0,%1,%2,%3}, {%4,%5,%6,%7}, {%8,%9}, {%0,%1,%2,%3};"
                 : "+f"(c0), "+f"(c1), "+f"(c2), "+f"(c3)
                 : "r"(a0), "r"(a1), "r"(a2), "r"(a3), "r"(b0), "r"(b1));
}

__device__ __forceinline__ uint32_t pack_h2(float x, float y) {
    __half2 h = __float22half2_rn(make_float2(x, y));
    return *(uint32_t*)&h;
}

__device__ __forceinline__ void cp_async16(uint32_t dst, const void* src) {
    asm volatile("cp.async.cg.shared.global [%0], [%1], 16;"
                 :: "r"(dst), "l"(src) : "memory");
}
#define CP_COMMIT()  asm volatile("cp.async.commit_group;" ::: "memory")
#define CP_WAIT(n)   asm volatile("cp.async.wait_group %0;" :: "n"(n) : "memory")

// ============================================================================
// Kernel 0 (unchanged from R16): out[:, 0:128]
// ============================================================================
#define K0_ST  136
#define K0_AST 136
#define K0_B0  0
#define K0_BS  512
#define K0_A0  35328
#define K0_A1  70144
#define K0_SMEM 104960

__global__ void __launch_bounds__(256, 2)
k0_mma(const float* __restrict__ x, const float* __restrict__ w0,
       const float* __restrict__ b0, float* __restrict__ out)
{
    extern __shared__ char smem[];
    float* b0s = (float*)(smem + K0_B0);

    const int tid  = threadIdx.x;
    const int wid  = tid >> 5;
    const int lane = tid & 31;
    const float a0 = 0.08838834764831845f;

    for (int idx = tid; idx < 128 * 128; idx += 256) {
        int n = idx & 127, k = idx >> 7;
        __half v = __float2half_rn(a0 * w0[k * 128 + n]);
        *(__half*)(smem + K0_BS + (n * K0_ST + k) * 2) = v;
    }
    if (tid < 128) b0s[tid] = b0[tid];
    __syncthreads();

    const int mh = wid >> 2;
    const int ns = wid & 3;
    const int lq = lane >> 2;
    const int kq = lane & 3;
    const int ak = kq * 2;

    const uint32_t ab0 = (uint32_t)__cvta_generic_to_shared(smem + K0_A0);
    const uint32_t ab1 = (uint32_t)__cvta_generic_to_shared(smem + K0_A1);

    int t = blockIdx.x;
    if (t < NTILES) {
        const int row0 = t * BM;
        #pragma unroll
        for (int it = 0; it < 8; it++) {
            int i = tid + it * 256;
            int r = i >> 5, c4 = (i & 31) << 2;
            cp_async16(ab0 + (uint32_t)(r * K0_AST + c4) * 4u,
                       x + (size_t)(row0 + r) * LDIM + c4);
        }
        CP_COMMIT();
    }

    int cur = 0;
    for (; t < NTILES; t += gridDim.x) {
        const int row0 = t * BM;
        const int tn = t + gridDim.x;

        if (tn < NTILES) {
            const int nrow0 = tn * BM;
            const uint32_t nb = cur ? ab0 : ab1;
            #pragma unroll
            for (int it = 0; it < 8; it++) {
                int i = tid + it * 256;
                int r = i >> 5, c4 = (i & 31) << 2;
                cp_async16(nb + (uint32_t)(r * K0_AST + c4) * 4u,
                           x + (size_t)(nrow0 + r) * LDIM + c4);
            }
            CP_COMMIT();
            CP_WAIT(1);
        } else {
            CP_WAIT(0);
        }
        __syncthreads();

        const float* A = (const float*)(smem + (cur ? K0_A1 : K0_A0));

        float C[2][4][4];
        #pragma unroll
        for (int nt = 0; nt < 4; nt++) {
            float bias0 = b0s[ns * 32 + nt * 8 + ak];
            float bias1 = b0s[ns * 32 + nt * 8 + ak + 1];
            #pragma unroll
            for (int mt = 0; mt < 2; mt++) {
                C[mt][nt][0] = bias0; C[mt][nt][1] = bias1;
                C[mt][nt][2] = bias0; C[mt][nt][3] = bias1;
            }
        }

        #pragma unroll
        for (int ks = 0; ks < 8; ks++) {
            const int k = ks * 16 + ak;
            uint32_t a[2][4];
            #pragma unroll
            for (int mt = 0; mt < 2; mt++) {
                const int ar = mh * 32 + mt * 16 + lq;
                const float* ap = A + ar * K0_AST + k;
                float2 f0 = *(const float2*)(ap);
                float2 f1 = *(const float2*)(ap + 8 * K0_AST);
                float2 f2 = *(const float2*)(ap + 8);
                float2 f3 = *(const float2*)(ap + 8 * K0_AST + 8);
                a[mt][0] = pack_h2(f0.x, f0.y);
                a[mt][1] = pack_h2(f1.x, f1.y);
                a[mt][2] = pack_h2(f2.x, f2.y);
                a[mt][3] = pack_h2(f3.x, f3.y);
            }
            #pragma unroll
            for (int nt = 0; nt < 4; nt++) {
                const int bn = ns * 32 + nt * 8 + lq;
                const char* bp = smem + K0_BS + (uint32_t)(bn * K0_ST + k) * 2u;
                uint32_t bv0 = *(const uint32_t*)(bp);
                uint32_t bv1 = *(const uint32_t*)(bp + 16);
                #pragma unroll
                for (int mt = 0; mt < 2; mt++)
                    mma_f16(C[mt][nt][0], C[mt][nt][1], C[mt][nt][2], C[mt][nt][3],
                            a[mt][0], a[mt][1], a[mt][2], a[mt][3], bv0, bv1);
            }
        }

        #pragma unroll
        for (int mt = 0; mt < 2; mt++) {
            const int grow = row0 + mh * 32 + mt * 16 + lq;
            #pragma unroll
            for (int nt = 0; nt < 4; nt++) {
                float* o0 = out + (size_t)grow * LDIM + ns * 32 + nt * 8 + ak;
                *(float2*)o0              = make_float2(C[mt][nt][0], C[mt][nt][1]);
                *(float2*)(o0 + 8 * LDIM) = make_float2(C[mt][nt][2], C[mt][nt][3]);
            }
        }
        __syncthreads();
        cur ^= 1;
    }
}

// ============================================================================
// Kernel 1 (fp16, OUT overlaid on A-stage -> 3 CTAs/SM): out[:, 128+3w+i]
// smem: Bs[0,9216) As[9216,36864) OUT overlay [9216,59392). Total 59392.
// ============================================================================
#define K1_ST 72
#define K1_BS 0
#define K1_AS 9216
#define K1_ABLK 9216
#define K1_OUT 9216           // overlay on As
#define K1_OST 196
#define K1_SMEM 59392

__global__ void __launch_bounds__(256, 3)
k1_mma(const float* __restrict__ x, const float* __restrict__ w1,
       float* __restrict__ out)
{
    extern __shared__ char smem[];
    const int tid  = threadIdx.x;
    const int wid  = tid >> 5;
    const int lane = tid & 31;
    const float a1 = 0.125f;

    for (int idx = tid; idx < 64 * 64; idx += 256) {
        int u = idx >> 6, w = idx & 63;
        *(__half*)(smem + K1_BS + (w * K1_ST + u) * 2) = __float2half_rn(a1 * w1[idx]);
    }

    const int mt = wid >> 1;
    const int nh = wid & 1;
    const int lq = lane >> 2;
    const int kq = lane & 3;
    const int ak = kq * 2;
    const int np = (lane & 3) * 2;

    for (int t = blockIdx.x; t < NTILES; t += gridDim.x) {
        const int row0 = t * BM;
        __syncthreads();   // prior store done before staging overwrites overlay

        #pragma unroll
        for (int it = 0; it < 4; it++) {
            int i = tid + it * 256;
            int r = i >> 4, g = i & 15;
            const float* xp = x + (size_t)(row0 + r) * LDIM + 128 + g * 12;
            float f[12];
            *(float4*)(f)     = *(const float4*)(xp);
            *(float4*)(f + 4) = *(const float4*)(xp + 4);
            *(float4*)(f + 8) = *(const float4*)(xp + 8);
            #pragma unroll
            for (int ch = 0; ch < 3; ch++) {
                uint2 p = make_uint2(pack_h2(f[ch], f[ch + 3]),
                                     pack_h2(f[ch + 6], f[ch + 9]));
                *(uint2*)(smem + K1_AS + ch * K1_ABLK
                          + (uint32_t)(r * K1_ST + 4 * g) * 2u) = p;
            }
        }
        __syncthreads();

        float C[3][4][4];
        #pragma unroll
        for (int ch = 0; ch < 3; ch++) {
            const char* Ab = smem + K1_AS + ch * K1_ABLK;
            uint32_t a[4][4];
            #pragma unroll
            for (int ks = 0; ks < 4; ks++) {
                const char* ap = Ab + (uint32_t)((mt * 16 + lq) * K1_ST + ks * 16 + ak) * 2u;
                a[ks][0] = *(const uint32_t*)(ap);
                a[ks][1] = *(const uint32_t*)(ap + 8 * K1_ST * 2);
                a[ks][2] = *(const uint32_t*)(ap + 16);
                a[ks][3] = *(const uint32_t*)(ap + 8 * K1_ST * 2 + 16);
            }
            #pragma unroll
            for (int q = 0; q < 4; q++) {
                const int nt = nh * 4 + q;
                float c0 = 0.f, c1 = 0.f, c2 = 0.f, c3 = 0.f;
                const int bn = nt * 8 + lq;
                #pragma unroll
                for (int ks = 0; ks < 4; ks++) {
                    const char* bp = smem + K1_BS
                                   + (uint32_t)(bn * K1_ST + ks * 16 + ak) * 2u;
                    uint32_t bv0 = *(const uint32_t*)(bp);
                    uint32_t bv1 = *(const uint32_t*)(bp + 16);
                    mma_f16(c0, c1, c2, c3, a[ks][0], a[ks][1], a[ks][2], a[ks][3], bv0, bv1);
                }
                C[ch][q][0] = c0; C[ch][q][1] = c1; C[ch][q][2] = c2; C[ch][q][3] = c3;
            }
        }
        __syncthreads();   // A reads done -> overlay becomes out-stage

        float* st = (float*)(smem + K1_OUT);
        {
            const int rA = mt * 16 + lq;
            #pragma unroll
            for (int ch = 0; ch < 3; ch++) {
                #pragma unroll
                for (int q = 0; q < 4; q++) {
                    const int n0 = (nh * 4 + q) * 8 + np;
                    const int col = 3 * n0 + ch;
                    st[rA * K1_OST + col]           = C[ch][q][0];
                    st[rA * K1_OST + col + 3]       = C[ch][q][1];
                    st[(rA + 8) * K1_OST + col]     = C[ch][q][2];
                    st[(rA + 8) * K1_OST + col + 3] = C[ch][q][3];
                }
            }
        }
        __syncthreads();

        #pragma unroll
        for (int it = 0; it < 12; it++) {
            int i = tid + it * 256;
            int r = i / 48, c4 = (i - r * 48) * 4;
            float4 v = *(const float4*)(st + r * K1_OST + c4);
            *(float4*)(out + (size_t)(row0 + r) * LDIM + 128 + c4) = v;
        }
    }
}

// ============================================================================
// Kernel 2 (fp16, C in regs + OUT overlay -> 3 CTAs/SM): out[:, 320+5w+i]
// smem: Bs[0,2560) As[2560,28160) OUT overlay [2560,44544). Total 44544.
// ============================================================================
#define K2_ST 40
#define K2_BS 0
#define K2_AS 2560
#define K2_ABLK 5120
#define K2_OUT 2560           // overlay on As
#define K2_OST 164
#define K2_SMEM 44544

__global__ void __launch_bounds__(256, 3)
k2_mma(const float* __restrict__ x, const float* __restrict__ w2,
       float* __restrict__ out)
{
    extern __shared__ char smem[];
    const int tid  = threadIdx.x;
    const int wid  = tid >> 5;
    const int lane = tid & 31;
    const float a2 = 0.17677669529663687f;

    for (int idx = tid; idx < 32 * 32; idx += 256) {
        int u = idx >> 5, w = idx & 31;
        *(__half*)(smem + K2_BS + (w * K2_ST + u) * 2) = __float2half_rn(a2 * w2[idx]);
    }

    const int mt = wid >> 1;
    const int nh = wid & 1;
    const int lq = lane >> 2;
    const int kq = lane & 3;
    const int ak = kq * 2;
    const int np = (lane & 3) * 2;

    for (int t = blockIdx.x; t < NTILES; t += gridDim.x) {
        const int row0 = t * BM;
        __syncthreads();   // prior store done before staging overwrites overlay

        #pragma unroll
        for (int it = 0; it < 2; it++) {
            int i = tid + it * 256;
            int r = i >> 3, g = i & 7;
            const float* xp = x + (size_t)(row0 + r) * LDIM + 320 + g * 20;
            float f[20];
            #pragma unroll
            for (int q = 0; q < 5; q++)
                *(float4*)(f + 4 * q) = *(const float4*)(xp + 4 * q);
            #pragma unroll
            for (int ch = 0; ch < 5; ch++) {
                uint2 p = make_uint2(pack_h2(f[ch], f[ch + 5]),
                                     pack_h2(f[ch + 10], f[ch + 15]));
                *(uint2*)(smem + K2_AS + ch * K2_ABLK
                          + (uint32_t)(r * K2_ST + 4 * g) * 2u) = p;
            }
        }
        __syncthreads();

        const int rA = mt * 16 + lq;
        float C[5][2][4];
        #pragma unroll
        for (int ch = 0; ch < 5; ch++) {
            const char* Ab = smem + K2_AS + ch * K2_ABLK;
            uint32_t a[2][4];
            #pragma unroll
            for (int ks = 0; ks < 2; ks++) {
                const char* ap = Ab + (uint32_t)(rA * K2_ST + ks * 16 + ak) * 2u;
                a[ks][0] = *(const uint32_t*)(ap);
                a[ks][1] = *(const uint32_t*)(ap + 8 * K2_ST * 2);
                a[ks][2] = *(const uint32_t*)(ap + 16);
                a[ks][3] = *(const uint32_t*)(ap + 8 * K2_ST * 2 + 16);
            }
            #pragma unroll
            for (int q = 0; q < 2; q++) {
                const int nt = nh * 2 + q;
                float c0 = 0.f, c1 = 0.f, c2 = 0.f, c3 = 0.f;
                const int bn = nt * 8 + lq;
                #pragma unroll
                for (int ks = 0; ks < 2; ks++) {
                    const char* bp = smem + K2_BS
                                   + (uint32_t)(bn * K2_ST + ks * 16 + ak) * 2u;
                    uint32_t bv0 = *(const uint32_t*)(bp);
                    uint32_t bv1 = *(const uint32_t*)(bp + 16);
                    mma_f16(c0, c1, c2, c3, a[ks][0], a[ks][1], a[ks][2], a[ks][3], bv0, bv1);
                }
                C[ch][q][0] = c0; C[ch][q][1] = c1; C[ch][q][2] = c2; C[ch][q][3] = c3;
            }
        }
        __syncthreads();   // A reads done -> overlay becomes out-stage

        float* st = (float*)(smem + K2_OUT);
        #pragma unroll
        for (int ch = 0; ch < 5; ch++) {
            #pragma unroll
            for (int q = 0; q < 2; q++) {
                const int n0 = (nh * 2 + q) * 8 + np;
                const int col = 5 * n0 + ch;
                st[rA * K2_OST + col]           = C[ch][q][0];
                st[rA * K2_OST + col + 5]       = C[ch][q][1];
                st[(rA + 8) * K2_OST + col]     = C[ch][q][2];
                st[(rA + 8) * K2_OST + col + 5] = C[ch][q][3];
            }
        }
        __syncthreads();

        #pragma unroll
        for (int it = 0; it < 10; it++) {
            int i = tid + it * 256;
            int r = i / 40, c4 = (i - r * 40) * 4;
            float4 v = *(const float4*)(st + r * K2_OST + c4);
            *(float4*)(out + (size_t)(row0 + r) * LDIM + 320 + c4) = v;
        }
    }
}

// ============================================================================

extern "C" void kernel_launch(void* const* d_in, const int* in_sizes, int n_in,
                              void* d_out, int out_size)
{
    const float* x  = (const float*)d_in[0];
    const float* w0 = (const float*)d_in[1];
    const float* w1 = (const float*)d_in[2];
    const float* w2 = (const float*)d_in[3];
    const float* b0 = (const float*)d_in[4];
    float* out = (float*)d_out;

    cudaFuncSetAttribute(k0_mma, cudaFuncAttributeMaxDynamicSharedMemorySize, K0_SMEM);
    cudaFuncSetAttribute(k1_mma, cudaFuncAttributeMaxDynamicSharedMemorySize, K1_SMEM);
    cudaFuncSetAttribute(k2_mma, cudaFuncAttributeMaxDynamicSharedMemorySize, K2_SMEM);

    k0_mma<<<304, 256, K0_SMEM>>>(x, w0, b0, out);
    k1_mma<<<456, 256, K1_SMEM>>>(x, w1, out);
    k2_mma<<<456, 256, K2_SMEM>>>(x, w2, out);
}